// round 4
// baseline (speedup 1.0000x reference)
#include <cuda_runtime.h>
#include <math.h>

#define BB 2
#define SS 2048
#define DD 1024
#define HH 16
#define DP 64
#define MM (BB * SS)   // 4096

// Scratch (allocation-free rule: __device__ globals)
__device__ float g_q[MM * DD];
__device__ float g_k[MM * DD];
__device__ float g_v[MM * DD];
__device__ float g_c[MM * DD];

// ---------------------------------------------------------------------------
// Helpers: tf32 convert + m16n8k8 tf32 MMA
// ---------------------------------------------------------------------------
__device__ __forceinline__ unsigned f2tf(float x) {
    unsigned r;
    asm("cvt.rna.tf32.f32 %0, %1;" : "=r"(r) : "f"(x));
    return r;
}

__device__ __forceinline__ void mma8(float* c, const unsigned* a, const unsigned* b) {
    asm volatile(
        "mma.sync.aligned.m16n8k8.row.col.f32.tf32.tf32.f32 "
        "{%0,%1,%2,%3}, {%4,%5,%6,%7}, {%8,%9}, {%0,%1,%2,%3};"
        : "+f"(c[0]), "+f"(c[1]), "+f"(c[2]), "+f"(c[3])
        : "r"(a[0]), "r"(a[1]), "r"(a[2]), "r"(a[3]), "r"(b[0]), "r"(b[1]));
}

// ---------------------------------------------------------------------------
// Tensor-core SGEMM + bias (generic). Block 256 thr, tile 128x128, K-tile 32.
// ---------------------------------------------------------------------------
#define AS_STR 36
#define BS_STR 136

__device__ __forceinline__ void gemm_body(const float* __restrict__ A,
                                          const float* __restrict__ W,
                                          const float* __restrict__ bias,
                                          float* __restrict__ C,
                                          int Ndim, int Kdim,
                                          int m0, int n0,
                                          unsigned* As, unsigned* Bs) {
    const int tid = threadIdx.x;
    const int warp = tid >> 5, lane = tid & 31;
    const int g = lane >> 2, t = lane & 3;
    const int wm = warp >> 1, wn = warp & 1;

    float acc[2][8][4] = {};

    for (int k0 = 0; k0 < Kdim; k0 += 32) {
        #pragma unroll
        for (int i = tid; i < 1024; i += 256) {
            int r = i >> 3, c4 = (i & 7) * 4;
            float4 v = *(const float4*)(A + (size_t)(m0 + r) * Kdim + k0 + c4);
            As[r * AS_STR + c4 + 0] = f2tf(v.x);
            As[r * AS_STR + c4 + 1] = f2tf(v.y);
            As[r * AS_STR + c4 + 2] = f2tf(v.z);
            As[r * AS_STR + c4 + 3] = f2tf(v.w);
        }
        #pragma unroll
        for (int i = tid; i < 1024; i += 256) {
            int r = i >> 5, c4 = (i & 31) * 4;
            float4 v = *(const float4*)(W + (size_t)(k0 + r) * Ndim + n0 + c4);
            Bs[r * BS_STR + c4 + 0] = f2tf(v.x);
            Bs[r * BS_STR + c4 + 1] = f2tf(v.y);
            Bs[r * BS_STR + c4 + 2] = f2tf(v.z);
            Bs[r * BS_STR + c4 + 3] = f2tf(v.w);
        }
        __syncthreads();

        #pragma unroll
        for (int k = 0; k < 32; k += 8) {
            unsigned a[2][4], bfr[8][2];
            #pragma unroll
            for (int mt = 0; mt < 2; mt++) {
                int m = wm * 32 + mt * 16;
                a[mt][0] = As[(m + g) * AS_STR + k + t];
                a[mt][1] = As[(m + g + 8) * AS_STR + k + t];
                a[mt][2] = As[(m + g) * AS_STR + k + t + 4];
                a[mt][3] = As[(m + g + 8) * AS_STR + k + t + 4];
            }
            #pragma unroll
            for (int nt = 0; nt < 8; nt++) {
                int n = wn * 64 + nt * 8 + g;
                bfr[nt][0] = Bs[(k + t) * BS_STR + n];
                bfr[nt][1] = Bs[(k + t + 4) * BS_STR + n];
            }
            #pragma unroll
            for (int mt = 0; mt < 2; mt++)
                #pragma unroll
                for (int nt = 0; nt < 8; nt++)
                    mma8(acc[mt][nt], a[mt], bfr[nt]);
        }
        __syncthreads();
    }

    #pragma unroll
    for (int mt = 0; mt < 2; mt++) {
        int row = m0 + wm * 32 + mt * 16 + g;
        #pragma unroll
        for (int nt = 0; nt < 8; nt++) {
            int col = n0 + wn * 64 + nt * 8 + 2 * t;
            float b0 = bias[col], b1 = bias[col + 1];
            C[(size_t)row * Ndim + col]           = acc[mt][nt][0] + b0;
            C[(size_t)row * Ndim + col + 1]       = acc[mt][nt][1] + b1;
            C[(size_t)(row + 8) * Ndim + col]     = acc[mt][nt][2] + b0;
            C[(size_t)(row + 8) * Ndim + col + 1] = acc[mt][nt][3] + b1;
        }
    }
}

__global__ void sgemm_bias_tc(const float* __restrict__ A,
                              const float* __restrict__ W,
                              const float* __restrict__ bias,
                              float* __restrict__ C,
                              int Ndim, int Kdim) {
    __shared__ unsigned As[128 * AS_STR];
    __shared__ unsigned Bs[32 * BS_STR];
    gemm_body(A, W, bias, C, Ndim, Kdim,
              blockIdx.y * 128, blockIdx.x * 128, As, Bs);
}

// QKV fused: z selects (A, W, bias, out)
__global__ void qkv_gemm_tc(const float* __restrict__ A0, const float* __restrict__ A1,
                            const float* __restrict__ A2,
                            const float* __restrict__ W0, const float* __restrict__ W1,
                            const float* __restrict__ W2,
                            const float* __restrict__ b0, const float* __restrict__ b1,
                            const float* __restrict__ b2,
                            float* __restrict__ C0, float* __restrict__ C1,
                            float* __restrict__ C2) {
    __shared__ unsigned As[128 * AS_STR];
    __shared__ unsigned Bs[32 * BS_STR];
    const int z = blockIdx.z;
    const float* A = (z == 0) ? A0 : (z == 1) ? A1 : A2;
    const float* W = (z == 0) ? W0 : (z == 1) ? W1 : W2;
    const float* bs = (z == 0) ? b0 : (z == 1) ? b1 : b2;
    float* C = (z == 0) ? C0 : (z == 1) ? C1 : C2;
    gemm_body(A, W, bs, C, DD, DD, blockIdx.y * 128, blockIdx.x * 128, As, Bs);
}

// ---------------------------------------------------------------------------
// Fused attention: scores + online softmax + normalized-attn write + AV.
// Block = 256 thr, handles (z, 128 q-rows). 8 warps as 4x2 (wm,wn).
// Phase A: loop K-tiles(128): logits->attn (raw), running rowmax/rowsum.
// Phase B: loop K-tiles: read raw logits (L2-hot), p=exp(x-m)/s -> attn,
//          and p @ V via MMA -> ctx.
// ---------------------------------------------------------------------------
#define QS_STR 68
#define PS_STR 132
#define VS2_STR 72
// dynamic smem (u32 units): Qs[128*68] + Ks[128*68] | As[128*132] alias,
// then Vs[128*72], then pmax[256],psum[256],rowm[128],rowinv[128]
#define SM_KS   (128 * QS_STR)
#define SM_VS   (2 * 128 * QS_STR)
#define SM_AUX  (SM_VS + 128 * VS2_STR)
#define ATTN_SMEM_BYTES ((SM_AUX + 768) * 4)

__global__ void attn_fused(const float* __restrict__ Q,
                           const float* __restrict__ K,
                           const float* __restrict__ V,
                           const float* __restrict__ mask,
                           float* __restrict__ attn,
                           float* __restrict__ C) {
    extern __shared__ unsigned sm[];
    unsigned* Qs = sm;            // [128][68] (phase A)
    unsigned* Ks = sm + SM_KS;    // [128][68] (phase A)
    unsigned* As = sm;            // [128][132] (phase B, aliases Qs/Ks)
    unsigned* Vs = sm + SM_VS;    // [128][72] (phase B)
    float* pmax   = (float*)(sm + SM_AUX);   // [128][2]
    float* psum   = pmax + 256;              // [128][2]
    float* rowm   = psum + 256;              // [128]
    float* rowinv = rowm + 128;              // [128]

    const int z = blockIdx.y;
    const int b = z >> 4, h = z & 15;
    const int q0 = blockIdx.x * 128;
    const int tid = threadIdx.x;
    const int warp = tid >> 5, lane = tid & 31;
    const int g = lane >> 2, t = lane & 3;
    const int wm = warp >> 1, wn = warp & 1;

    // ---- load Q tile (stays resident through phase A) ----
    const float* Qb = Q + (size_t)(b * SS + q0) * DD + h * DP;
    #pragma unroll
    for (int i = tid; i < 128 * 16; i += 256) {
        int r = i >> 4, c4 = (i & 15) * 4;
        float4 vq = *(const float4*)(Qb + (size_t)r * DD + c4);
        Qs[r * QS_STR + c4 + 0] = f2tf(vq.x);
        Qs[r * QS_STR + c4 + 1] = f2tf(vq.y);
        Qs[r * QS_STR + c4 + 2] = f2tf(vq.z);
        Qs[r * QS_STR + c4 + 3] = f2tf(vq.w);
    }

    float m_run[2][2], s_run[2][2];
    #pragma unroll
    for (int mt = 0; mt < 2; mt++)
        #pragma unroll
        for (int hi = 0; hi < 2; hi++) { m_run[mt][hi] = -1e30f; s_run[mt][hi] = 0.f; }

    // =============================== Phase A ===============================
    for (int k0 = 0; k0 < SS; k0 += 128) {
        const float* Kb = K + (size_t)(b * SS + k0) * DD + h * DP;
        #pragma unroll
        for (int i = tid; i < 128 * 16; i += 256) {
            int r = i >> 4, c4 = (i & 15) * 4;
            float4 vk = *(const float4*)(Kb + (size_t)r * DD + c4);
            Ks[r * QS_STR + c4 + 0] = f2tf(vk.x);
            Ks[r * QS_STR + c4 + 1] = f2tf(vk.y);
            Ks[r * QS_STR + c4 + 2] = f2tf(vk.z);
            Ks[r * QS_STR + c4 + 3] = f2tf(vk.w);
        }
        __syncthreads();

        float acc[2][8][4] = {};
        #pragma unroll
        for (int d = 0; d < 64; d += 8) {
            unsigned a[2][4], bfr[8][2];
            #pragma unroll
            for (int mt = 0; mt < 2; mt++) {
                int m = wm * 32 + mt * 16;
                a[mt][0] = Qs[(m + g) * QS_STR + d + t];
                a[mt][1] = Qs[(m + g + 8) * QS_STR + d + t];
                a[mt][2] = Qs[(m + g) * QS_STR + d + t + 4];
                a[mt][3] = Qs[(m + g + 8) * QS_STR + d + t + 4];
            }
            #pragma unroll
            for (int nt = 0; nt < 8; nt++) {
                int n = wn * 64 + nt * 8 + g;
                bfr[nt][0] = Ks[n * QS_STR + d + t];
                bfr[nt][1] = Ks[n * QS_STR + d + t + 4];
            }
            #pragma unroll
            for (int mt = 0; mt < 2; mt++)
                #pragma unroll
                for (int nt = 0; nt < 8; nt++)
                    mma8(acc[mt][nt], a[mt], bfr[nt]);
        }

        // scale + mask (in place)
        #pragma unroll
        for (int mt = 0; mt < 2; mt++)
            #pragma unroll
            for (int nt = 0; nt < 8; nt++) {
                int kj = k0 + wn * 64 + nt * 8 + 2 * t;
                float mk0 = mask[b * SS + kj] * (-1e9f);
                float mk1 = mask[b * SS + kj + 1] * (-1e9f);
                acc[mt][nt][0] = acc[mt][nt][0] * 0.125f + mk0;
                acc[mt][nt][1] = acc[mt][nt][1] * 0.125f + mk1;
                acc[mt][nt][2] = acc[mt][nt][2] * 0.125f + mk0;
                acc[mt][nt][3] = acc[mt][nt][3] * 0.125f + mk1;
            }

        // row max (warp-half), combine across wn via smem
        #pragma unroll
        for (int mt = 0; mt < 2; mt++)
            #pragma unroll
            for (int hi = 0; hi < 2; hi++) {
                float mx = -1e30f;
                #pragma unroll
                for (int nt = 0; nt < 8; nt++)
                    mx = fmaxf(mx, fmaxf(acc[mt][nt][2 * hi], acc[mt][nt][2 * hi + 1]));
                mx = fmaxf(mx, __shfl_xor_sync(~0u, mx, 1));
                mx = fmaxf(mx, __shfl_xor_sync(~0u, mx, 2));
                if (t == 0) pmax[(wm * 32 + mt * 16 + g + 8 * hi) * 2 + wn] = mx;
            }
        __syncthreads();

        float mnew[2][2];
        #pragma unroll
        for (int mt = 0; mt < 2; mt++)
            #pragma unroll
            for (int hi = 0; hi < 2; hi++) {
                int row = wm * 32 + mt * 16 + g + 8 * hi;
                float tm = fmaxf(pmax[row * 2], pmax[row * 2 + 1]);
                float mn = fmaxf(m_run[mt][hi], tm);
                mnew[mt][hi] = mn;
                float ls = 0.f;
                #pragma unroll
                for (int nt = 0; nt < 8; nt++)
                    ls += __expf(acc[mt][nt][2 * hi] - mn) +
                          __expf(acc[mt][nt][2 * hi + 1] - mn);
                ls += __shfl_xor_sync(~0u, ls, 1);
                ls += __shfl_xor_sync(~0u, ls, 2);
                if (t == 0) psum[row * 2 + wn] = ls;
            }
        __syncthreads();

        #pragma unroll
        for (int mt = 0; mt < 2; mt++)
            #pragma unroll
            for (int hi = 0; hi < 2; hi++) {
                int row = wm * 32 + mt * 16 + g + 8 * hi;
                float ts = psum[row * 2] + psum[row * 2 + 1];
                float corr = __expf(m_run[mt][hi] - mnew[mt][hi]);
                s_run[mt][hi] = s_run[mt][hi] * corr + ts;
                m_run[mt][hi] = mnew[mt][hi];
            }

        // write raw logits
        #pragma unroll
        for (int mt = 0; mt < 2; mt++) {
            int qi = q0 + wm * 32 + mt * 16 + g;
            size_t base0 = ((size_t)z * SS + qi) * SS;
            size_t base1 = base0 + (size_t)8 * SS;
            #pragma unroll
            for (int nt = 0; nt < 8; nt++) {
                int kj = k0 + wn * 64 + nt * 8 + 2 * t;
                attn[base0 + kj]     = acc[mt][nt][0];
                attn[base0 + kj + 1] = acc[mt][nt][1];
                attn[base1 + kj]     = acc[mt][nt][2];
                attn[base1 + kj + 1] = acc[mt][nt][3];
            }
        }
        __syncthreads();
    }

    // publish per-row stats
    if (wn == 0 && t == 0) {
        #pragma unroll
        for (int mt = 0; mt < 2; mt++)
            #pragma unroll
            for (int hi = 0; hi < 2; hi++) {
                int row = wm * 32 + mt * 16 + g + 8 * hi;
                rowm[row] = m_run[mt][hi];
                rowinv[row] = 1.0f / s_run[mt][hi];
            }
    }
    __syncthreads();

    // =============================== Phase B ===============================
    float acc2[2][4][4] = {};
    for (int k0 = 0; k0 < SS; k0 += 128) {
        // finish softmax on this tile: read raw -> p -> write attn + smem As
        #pragma unroll
        for (int i = tid; i < 128 * 32; i += 256) {
            int r = i >> 5, c4 = (i & 31) * 4;
            size_t addr = ((size_t)z * SS + q0 + r) * SS + k0 + c4;
            float4 x = *(float4*)(attn + addr);
            float m = rowm[r], inv = rowinv[r];
            x.x = __expf(x.x - m) * inv;
            x.y = __expf(x.y - m) * inv;
            x.z = __expf(x.z - m) * inv;
            x.w = __expf(x.w - m) * inv;
            *(float4*)(attn + addr) = x;
            As[r * PS_STR + c4 + 0] = f2tf(x.x);
            As[r * PS_STR + c4 + 1] = f2tf(x.y);
            As[r * PS_STR + c4 + 2] = f2tf(x.z);
            As[r * PS_STR + c4 + 3] = f2tf(x.w);
        }
        // V tile: [128 k][64 d]
        #pragma unroll
        for (int i = tid; i < 128 * 16; i += 256) {
            int r = i >> 4, c4 = (i & 15) * 4;
            float4 vv = *(const float4*)(V + (size_t)(b * SS + k0 + r) * DD + h * DP + c4);
            Vs[r * VS2_STR + c4 + 0] = f2tf(vv.x);
            Vs[r * VS2_STR + c4 + 1] = f2tf(vv.y);
            Vs[r * VS2_STR + c4 + 2] = f2tf(vv.z);
            Vs[r * VS2_STR + c4 + 3] = f2tf(vv.w);
        }
        __syncthreads();

        #pragma unroll
        for (int kk = 0; kk < 128; kk += 8) {
            unsigned a[2][4], bfr[4][2];
            #pragma unroll
            for (int mt = 0; mt < 2; mt++) {
                int m = wm * 32 + mt * 16;
                a[mt][0] = As[(m + g) * PS_STR + kk + t];
                a[mt][1] = As[(m + g + 8) * PS_STR + kk + t];
                a[mt][2] = As[(m + g) * PS_STR + kk + t + 4];
                a[mt][3] = As[(m + g + 8) * PS_STR + kk + t + 4];
            }
            #pragma unroll
            for (int nt = 0; nt < 4; nt++) {
                int n = wn * 32 + nt * 8 + g;
                bfr[nt][0] = Vs[(kk + t) * VS2_STR + n];
                bfr[nt][1] = Vs[(kk + t + 4) * VS2_STR + n];
            }
            #pragma unroll
            for (int mt = 0; mt < 2; mt++)
                #pragma unroll
                for (int nt = 0; nt < 4; nt++)
                    mma8(acc2[mt][nt], a[mt], bfr[nt]);
        }
        __syncthreads();
    }

    // write ctx
    #pragma unroll
    for (int mt = 0; mt < 2; mt++) {
        int qi = q0 + wm * 32 + mt * 16 + g;
        size_t base0 = (size_t)(b * SS + qi) * DD + h * DP;
        size_t base1 = base0 + (size_t)8 * DD;
        #pragma unroll
        for (int nt = 0; nt < 4; nt++) {
            int dj = wn * 32 + nt * 8 + 2 * t;
            C[base0 + dj]     = acc2[mt][nt][0];
            C[base0 + dj + 1] = acc2[mt][nt][1];
            C[base1 + dj]     = acc2[mt][nt][2];
            C[base1 + dj + 1] = acc2[mt][nt][3];
        }
    }
}

// ---------------------------------------------------------------------------
extern "C" void kernel_launch(void* const* d_in, const int* in_sizes, int n_in,
                              void* d_out, int out_size) {
    const float* q    = (const float*)d_in[0];
    const float* k    = (const float*)d_in[1];
    const float* v    = (const float*)d_in[2];
    const float* mask = (const float*)d_in[3];
    const float* Wq   = (const float*)d_in[4];
    const float* bq   = (const float*)d_in[5];
    const float* Wk   = (const float*)d_in[6];
    const float* bk   = (const float*)d_in[7];
    const float* Wv   = (const float*)d_in[8];
    const float* bv   = (const float*)d_in[9];
    const float* Wo   = (const float*)d_in[10];
    const float* bo   = (const float*)d_in[11];

    float* out  = (float*)d_out;
    float* attn = out + (size_t)MM * DD;   // output layout: (out, attn)

    float *pq, *pk, *pv, *pc;
    cudaGetSymbolAddress((void**)&pq, g_q);
    cudaGetSymbolAddress((void**)&pk, g_k);
    cudaGetSymbolAddress((void**)&pv, g_v);
    cudaGetSymbolAddress((void**)&pc, g_c);

    static int smem_set = 0;
    if (!smem_set) {
        cudaFuncSetAttribute(attn_fused,
                             cudaFuncAttributeMaxDynamicSharedMemorySize,
                             ATTN_SMEM_BYTES);
        smem_set = 1;
    }

    dim3 gQKV(DD / 128, MM / 128, 3);               // (8, 32, 3)
    qkv_gemm_tc<<<gQKV, 256>>>(q, k, v, Wq, Wk, Wv, bq, bk, bv, pq, pk, pv);

    dim3 gAttn(SS / 128, BB * HH);                  // (16, 32)
    attn_fused<<<gAttn, 256, ATTN_SMEM_BYTES>>>(pq, pk, pv, mask, attn, pc);

    dim3 gProj(DD / 128, MM / 128);                 // (8, 32)
    sgemm_bias_tc<<<gProj, 256>>>(pc, Wo, bo, out, DD, DD);
}

// round 5
// speedup vs baseline: 1.4638x; 1.4638x over previous
#include <cuda_runtime.h>
#include <math.h>

#define BB 2
#define SS 2048
#define DD 1024
#define HH 16
#define DP 64
#define MM (BB * SS)   // 4096

// Scratch (allocation-free rule: __device__ globals)
__device__ float g_q[MM * DD];
__device__ float g_k[MM * DD];
__device__ float g_v[MM * DD];
__device__ float g_c[MM * DD];
__device__ float g_rowm[BB * HH * SS];
__device__ float g_rowinv[BB * HH * SS];

// ---------------------------------------------------------------------------
// Helpers
// ---------------------------------------------------------------------------
__device__ __forceinline__ unsigned f2tf(float x) {
    unsigned r;
    asm("cvt.rna.tf32.f32 %0, %1;" : "=r"(r) : "f"(x));
    return r;
}

__device__ __forceinline__ void mma8(float* c, const unsigned* a, const unsigned* b) {
    asm volatile(
        "mma.sync.aligned.m16n8k8.row.col.f32.tf32.tf32.f32 "
        "{%0,%1,%2,%3}, {%4,%5,%6,%7}, {%8,%9}, {%0,%1,%2,%3};"
        : "+f"(c[0]), "+f"(c[1]), "+f"(c[2]), "+f"(c[3])
        : "r"(a[0]), "r"(a[1]), "r"(a[2]), "r"(a[3]), "r"(b[0]), "r"(b[1]));
}

__device__ __forceinline__ unsigned smem_u32(const void* p) {
    unsigned r;
    asm("{ .reg .u64 t; cvta.to.shared.u64 t, %1; cvt.u32.u64 %0, t; }"
        : "=r"(r) : "l"(p));
    return r;
}

__device__ __forceinline__ void cpasync16(unsigned s, const void* g) {
    asm volatile("cp.async.cg.shared.global [%0], [%1], 16;" :: "r"(s), "l"(g));
}

// ---------------------------------------------------------------------------
// Pipelined tensor-core SGEMM + bias: C = A[M,K] @ W[K,N] + bias.
// Tile 128x128, K-tile 32, 2-stage cp.async double buffer, fp32 smem,
// tf32 cvt at fragment load. 8 warps 4x2, warp tile 32x64.
// ---------------------------------------------------------------------------
#define AS_STR 36
#define BS_STR 136
#define STG_F  (128 * AS_STR + 32 * BS_STR)   // floats per stage: 8960

__device__ __forceinline__ void gemm_load_tile(const float* __restrict__ A,
                                               const float* __restrict__ W,
                                               int Kdim, int Ndim,
                                               int m0, int n0, int k0,
                                               float* stage) {
    const int tid = threadIdx.x;
    unsigned sA = smem_u32(stage);
    unsigned sB = smem_u32(stage + 128 * AS_STR);
    #pragma unroll
    for (int i = tid; i < 1024; i += 256) {
        int r = i >> 3, c4 = (i & 7) * 4;
        cpasync16(sA + (r * AS_STR + c4) * 4, A + (size_t)(m0 + r) * Kdim + k0 + c4);
    }
    #pragma unroll
    for (int i = tid; i < 1024; i += 256) {
        int r = i >> 5, c4 = (i & 31) * 4;
        cpasync16(sB + (r * BS_STR + c4) * 4, W + (size_t)(k0 + r) * Ndim + n0 + c4);
    }
    asm volatile("cp.async.commit_group;");
}

__device__ __forceinline__ void gemm_body(const float* __restrict__ A,
                                          const float* __restrict__ W,
                                          const float* __restrict__ bias,
                                          float* __restrict__ C,
                                          int Ndim, int Kdim,
                                          int m0, int n0,
                                          float* smf) {
    const int tid = threadIdx.x;
    const int warp = tid >> 5, lane = tid & 31;
    const int g = lane >> 2, t = lane & 3;
    const int wm = warp >> 1, wn = warp & 1;

    float acc[2][8][4] = {};

    gemm_load_tile(A, W, Kdim, Ndim, m0, n0, 0, smf);

    int s = 0;
    for (int k0 = 0; k0 < Kdim; k0 += 32, s ^= 1) {
        if (k0 + 32 < Kdim) {
            gemm_load_tile(A, W, Kdim, Ndim, m0, n0, k0 + 32, smf + (s ^ 1) * STG_F);
            asm volatile("cp.async.wait_group 1;");
        } else {
            asm volatile("cp.async.wait_group 0;");
        }
        __syncthreads();

        const float* As = smf + s * STG_F;
        const float* Bs = As + 128 * AS_STR;

        #pragma unroll
        for (int k = 0; k < 32; k += 8) {
            unsigned a[2][4], bfr[8][2];
            #pragma unroll
            for (int mt = 0; mt < 2; mt++) {
                int m = wm * 32 + mt * 16;
                a[mt][0] = f2tf(As[(m + g) * AS_STR + k + t]);
                a[mt][1] = f2tf(As[(m + g + 8) * AS_STR + k + t]);
                a[mt][2] = f2tf(As[(m + g) * AS_STR + k + t + 4]);
                a[mt][3] = f2tf(As[(m + g + 8) * AS_STR + k + t + 4]);
            }
            #pragma unroll
            for (int nt = 0; nt < 8; nt++) {
                int n = wn * 64 + nt * 8 + g;
                bfr[nt][0] = f2tf(Bs[(k + t) * BS_STR + n]);
                bfr[nt][1] = f2tf(Bs[(k + t + 4) * BS_STR + n]);
            }
            #pragma unroll
            for (int mt = 0; mt < 2; mt++)
                #pragma unroll
                for (int nt = 0; nt < 8; nt++)
                    mma8(acc[mt][nt], a[mt], bfr[nt]);
        }
        __syncthreads();
    }

    #pragma unroll
    for (int mt = 0; mt < 2; mt++) {
        int row = m0 + wm * 32 + mt * 16 + g;
        #pragma unroll
        for (int nt = 0; nt < 8; nt++) {
            int col = n0 + wn * 64 + nt * 8 + 2 * t;
            float b0 = bias[col], b1 = bias[col + 1];
            C[(size_t)row * Ndim + col]           = acc[mt][nt][0] + b0;
            C[(size_t)row * Ndim + col + 1]       = acc[mt][nt][1] + b1;
            C[(size_t)(row + 8) * Ndim + col]     = acc[mt][nt][2] + b0;
            C[(size_t)(row + 8) * Ndim + col + 1] = acc[mt][nt][3] + b1;
        }
    }
}

#define GEMM_SMEM_BYTES (2 * STG_F * 4)   // 71680

__global__ void sgemm_bias_tc(const float* __restrict__ A,
                              const float* __restrict__ W,
                              const float* __restrict__ bias,
                              float* __restrict__ C,
                              int Ndim, int Kdim) {
    extern __shared__ float smf[];
    gemm_body(A, W, bias, C, Ndim, Kdim, blockIdx.y * 128, blockIdx.x * 128, smf);
}

__global__ void qkv_gemm_tc(const float* __restrict__ A0, const float* __restrict__ A1,
                            const float* __restrict__ A2,
                            const float* __restrict__ W0, const float* __restrict__ W1,
                            const float* __restrict__ W2,
                            const float* __restrict__ b0, const float* __restrict__ b1,
                            const float* __restrict__ b2,
                            float* __restrict__ C0, float* __restrict__ C1,
                            float* __restrict__ C2) {
    extern __shared__ float smf[];
    const int z = blockIdx.z;
    const float* A = (z == 0) ? A0 : (z == 1) ? A1 : A2;
    const float* W = (z == 0) ? W0 : (z == 1) ? W1 : W2;
    const float* bs = (z == 0) ? b0 : (z == 1) ? b1 : b2;
    float* C = (z == 0) ? C0 : (z == 1) ? C1 : C2;
    gemm_body(A, W, bs, C, DD, DD, blockIdx.y * 128, blockIdx.x * 128, smf);
}

// ---------------------------------------------------------------------------
// Attention scores (tensor core): writes RAW logits (scaled + masked).
// Block: 128 q x 128 k, depth=64 resident in smem. (round-3 proven kernel)
// ---------------------------------------------------------------------------
#define QS_STR 68
#define SCORES_SMEM_BYTES (2 * 128 * QS_STR * 4)
__global__ void attn_scores_tc(const float* __restrict__ Q,
                               const float* __restrict__ K,
                               const float* __restrict__ mask,
                               float* __restrict__ attn) {
    extern __shared__ unsigned sm[];
    unsigned* Qs = sm;                  // [128][68]
    unsigned* Ks = sm + 128 * QS_STR;   // [128][68]

    const int z = blockIdx.z;
    const int b = z >> 4;
    const int h = z & 15;
    const int q0 = blockIdx.y * 128, k0 = blockIdx.x * 128;
    const int tid = threadIdx.x;
    const int warp = tid >> 5, lane = tid & 31;
    const int g = lane >> 2, t = lane & 3;
    const int wm = warp >> 1, wn = warp & 1;

    const float* Qb = Q + (size_t)(b * SS + q0) * DD + h * DP;
    const float* Kb = K + (size_t)(b * SS + k0) * DD + h * DP;

    #pragma unroll
    for (int i = tid; i < 128 * 16; i += 256) {
        int r = i >> 4, c4 = (i & 15) * 4;
        float4 vq = *(const float4*)(Qb + (size_t)r * DD + c4);
        float4 vk = *(const float4*)(Kb + (size_t)r * DD + c4);
        Qs[r * QS_STR + c4 + 0] = f2tf(vq.x);
        Qs[r * QS_STR + c4 + 1] = f2tf(vq.y);
        Qs[r * QS_STR + c4 + 2] = f2tf(vq.z);
        Qs[r * QS_STR + c4 + 3] = f2tf(vq.w);
        Ks[r * QS_STR + c4 + 0] = f2tf(vk.x);
        Ks[r * QS_STR + c4 + 1] = f2tf(vk.y);
        Ks[r * QS_STR + c4 + 2] = f2tf(vk.z);
        Ks[r * QS_STR + c4 + 3] = f2tf(vk.w);
    }
    __syncthreads();

    float acc[2][8][4] = {};
    #pragma unroll
    for (int k = 0; k < 64; k += 8) {
        unsigned a[2][4], bfr[8][2];
        #pragma unroll
        for (int mt = 0; mt < 2; mt++) {
            int m = wm * 32 + mt * 16;
            a[mt][0] = Qs[(m + g) * QS_STR + k + t];
            a[mt][1] = Qs[(m + g + 8) * QS_STR + k + t];
            a[mt][2] = Qs[(m + g) * QS_STR + k + t + 4];
            a[mt][3] = Qs[(m + g + 8) * QS_STR + k + t + 4];
        }
        #pragma unroll
        for (int nt = 0; nt < 8; nt++) {
            int n = wn * 64 + nt * 8 + g;
            bfr[nt][0] = Ks[n * QS_STR + k + t];
            bfr[nt][1] = Ks[n * QS_STR + k + t + 4];
        }
        #pragma unroll
        for (int mt = 0; mt < 2; mt++)
            #pragma unroll
            for (int nt = 0; nt < 8; nt++)
                mma8(acc[mt][nt], a[mt], bfr[nt]);
    }

    #pragma unroll
    for (int mt = 0; mt < 2; mt++) {
        int qi = q0 + wm * 32 + mt * 16 + g;
        size_t base0 = ((size_t)z * SS + qi) * SS;
        size_t base1 = base0 + (size_t)8 * SS;
        #pragma unroll
        for (int nt = 0; nt < 8; nt++) {
            int kj = k0 + wn * 64 + nt * 8 + 2 * t;
            float mk0 = mask[b * SS + kj] * (-1e9f);
            float mk1 = mask[b * SS + kj + 1] * (-1e9f);
            attn[base0 + kj]     = acc[mt][nt][0] * 0.125f + mk0;
            attn[base0 + kj + 1] = acc[mt][nt][1] * 0.125f + mk1;
            attn[base1 + kj]     = acc[mt][nt][2] * 0.125f + mk0;
            attn[base1 + kj + 1] = acc[mt][nt][3] * 0.125f + mk1;
        }
    }
}

// ---------------------------------------------------------------------------
// Row stats: read raw logits, produce per-row max and 1/sum(exp(x-max)).
// One 256-thread block per row of 2048.
// ---------------------------------------------------------------------------
__global__ void stats_rows(const float* __restrict__ attn,
                           float* __restrict__ rowm,
                           float* __restrict__ rowinv) {
    const int row = blockIdx.x;
    const float4* p = (const float4*)(attn + (size_t)row * SS);
    const int tt = threadIdx.x;
    const int lane = tt & 31, warp = tt >> 5;

    __shared__ float red[8];

    float4 v0 = p[tt], v1 = p[tt + 256];
    float mx = fmaxf(fmaxf(fmaxf(v0.x, v0.y), fmaxf(v0.z, v0.w)),
                     fmaxf(fmaxf(v1.x, v1.y), fmaxf(v1.z, v1.w)));
    #pragma unroll
    for (int o = 16; o; o >>= 1) mx = fmaxf(mx, __shfl_xor_sync(~0u, mx, o));
    if (lane == 0) red[warp] = mx;
    __syncthreads();
    mx = red[0];
    #pragma unroll
    for (int i = 1; i < 8; i++) mx = fmaxf(mx, red[i]);
    __syncthreads();

    float sum = __expf(v0.x - mx) + __expf(v0.y - mx) + __expf(v0.z - mx) +
                __expf(v0.w - mx) + __expf(v1.x - mx) + __expf(v1.y - mx) +
                __expf(v1.z - mx) + __expf(v1.w - mx);
    #pragma unroll
    for (int o = 16; o; o >>= 1) sum += __shfl_xor_sync(~0u, sum, o);
    if (lane == 0) red[warp] = sum;
    __syncthreads();
    sum = red[0];
    #pragma unroll
    for (int i = 1; i < 8; i++) sum += red[i];

    if (tt == 0) {
        rowm[row] = mx;
        rowinv[row] = 1.0f / sum;
    }
}

// ---------------------------------------------------------------------------
// Fused normalize + AV: read raw logits, p = exp(x-m)*inv, write normalized
// attn, ctx += p @ V (tensor core). Block: 128 q x 64 d, K-tile 32.
// ---------------------------------------------------------------------------
#define VS_STR 72
__global__ void attn_av_norm(float* __restrict__ attn,
                             const float* __restrict__ V,
                             const float* __restrict__ rowm,
                             const float* __restrict__ rowinv,
                             float* __restrict__ C) {
    __shared__ unsigned As[128 * AS_STR];
    __shared__ unsigned Vs[32 * VS_STR];
    __shared__ float rs[128], ri[128];

    const int z = blockIdx.y;
    const int b = z >> 4;
    const int h = z & 15;
    const int q0 = blockIdx.x * 128;
    const int tid = threadIdx.x;
    const int warp = tid >> 5, lane = tid & 31;
    const int g = lane >> 2, t = lane & 3;
    const int wm = warp >> 1, wn = warp & 1;

    if (tid < 128) {
        rs[tid] = rowm[z * SS + q0 + tid];
        ri[tid] = rowinv[z * SS + q0 + tid];
    }
    __syncthreads();

    float acc[2][4][4] = {};

    for (int k0 = 0; k0 < SS; k0 += 32) {
        #pragma unroll
        for (int i = tid; i < 1024; i += 256) {
            int r = i >> 3, c4 = (i & 7) * 4;
            size_t addr = ((size_t)z * SS + q0 + r) * SS + k0 + c4;
            float4 x = *(float4*)(attn + addr);
            float m = rs[r], inv = ri[r];
            x.x = __expf(x.x - m) * inv;
            x.y = __expf(x.y - m) * inv;
            x.z = __expf(x.z - m) * inv;
            x.w = __expf(x.w - m) * inv;
            *(float4*)(attn + addr) = x;
            As[r * AS_STR + c4 + 0] = f2tf(x.x);
            As[r * AS_STR + c4 + 1] = f2tf(x.y);
            As[r * AS_STR + c4 + 2] = f2tf(x.z);
            As[r * AS_STR + c4 + 3] = f2tf(x.w);
        }
        #pragma unroll
        for (int i = tid; i < 512; i += 256) {
            int r = i >> 4, c4 = (i & 15) * 4;
            float4 v = *(const float4*)(V + (size_t)(b * SS + k0 + r) * DD + h * DP + c4);
            Vs[r * VS_STR + c4 + 0] = f2tf(v.x);
            Vs[r * VS_STR + c4 + 1] = f2tf(v.y);
            Vs[r * VS_STR + c4 + 2] = f2tf(v.z);
            Vs[r * VS_STR + c4 + 3] = f2tf(v.w);
        }
        __syncthreads();

        #pragma unroll
        for (int kk = 0; kk < 32; kk += 8) {
            unsigned a[2][4], bfr[4][2];
            #pragma unroll
            for (int mt = 0; mt < 2; mt++) {
                int m = wm * 32 + mt * 16;
                a[mt][0] = As[(m + g) * AS_STR + kk + t];
                a[mt][1] = As[(m + g + 8) * AS_STR + kk + t];
                a[mt][2] = As[(m + g) * AS_STR + kk + t + 4];
                a[mt][3] = As[(m + g + 8) * AS_STR + kk + t + 4];
            }
            #pragma unroll
            for (int nt = 0; nt < 4; nt++) {
                int n = wn * 32 + nt * 8 + g;
                bfr[nt][0] = Vs[(kk + t) * VS_STR + n];
                bfr[nt][1] = Vs[(kk + t + 4) * VS_STR + n];
            }
            #pragma unroll
            for (int mt = 0; mt < 2; mt++)
                #pragma unroll
                for (int nt = 0; nt < 4; nt++)
                    mma8(acc[mt][nt], a[mt], bfr[nt]);
        }
        __syncthreads();
    }

    #pragma unroll
    for (int mt = 0; mt < 2; mt++) {
        int qi = q0 + wm * 32 + mt * 16 + g;
        size_t base0 = (size_t)(b * SS + qi) * DD + h * DP;
        size_t base1 = base0 + (size_t)8 * DD;
        #pragma unroll
        for (int nt = 0; nt < 4; nt++) {
            int dj = wn * 32 + nt * 8 + 2 * t;
            C[base0 + dj]     = acc[mt][nt][0];
            C[base0 + dj + 1] = acc[mt][nt][1];
            C[base1 + dj]     = acc[mt][nt][2];
            C[base1 + dj + 1] = acc[mt][nt][3];
        }
    }
}

// ---------------------------------------------------------------------------
extern "C" void kernel_launch(void* const* d_in, const int* in_sizes, int n_in,
                              void* d_out, int out_size) {
    const float* q    = (const float*)d_in[0];
    const float* k    = (const float*)d_in[1];
    const float* v    = (const float*)d_in[2];
    const float* mask = (const float*)d_in[3];
    const float* Wq   = (const float*)d_in[4];
    const float* bq   = (const float*)d_in[5];
    const float* Wk   = (const float*)d_in[6];
    const float* bk   = (const float*)d_in[7];
    const float* Wv   = (const float*)d_in[8];
    const float* bv   = (const float*)d_in[9];
    const float* Wo   = (const float*)d_in[10];
    const float* bo   = (const float*)d_in[11];

    float* out  = (float*)d_out;
    float* attn = out + (size_t)MM * DD;   // output layout: (out, attn)

    float *pq, *pk, *pv, *pc, *prm, *pri;
    cudaGetSymbolAddress((void**)&pq, g_q);
    cudaGetSymbolAddress((void**)&pk, g_k);
    cudaGetSymbolAddress((void**)&pv, g_v);
    cudaGetSymbolAddress((void**)&pc, g_c);
    cudaGetSymbolAddress((void**)&prm, g_rowm);
    cudaGetSymbolAddress((void**)&pri, g_rowinv);

    cudaFuncSetAttribute(qkv_gemm_tc, cudaFuncAttributeMaxDynamicSharedMemorySize,
                         GEMM_SMEM_BYTES);
    cudaFuncSetAttribute(sgemm_bias_tc, cudaFuncAttributeMaxDynamicSharedMemorySize,
                         GEMM_SMEM_BYTES);
    cudaFuncSetAttribute(attn_scores_tc, cudaFuncAttributeMaxDynamicSharedMemorySize,
                         SCORES_SMEM_BYTES);

    dim3 gQKV(DD / 128, MM / 128, 3);               // (8, 32, 3)
    qkv_gemm_tc<<<gQKV, 256, GEMM_SMEM_BYTES>>>(q, k, v, Wq, Wk, Wv, bq, bk, bv,
                                                pq, pk, pv);

    dim3 gScores(SS / 128, SS / 128, BB * HH);      // (16, 16, 32)
    attn_scores_tc<<<gScores, 256, SCORES_SMEM_BYTES>>>(pq, pk, mask, attn);

    stats_rows<<<BB * HH * SS, 256>>>(attn, prm, pri);

    dim3 gAV(SS / 128, BB * HH);                    // (16, 32)
    attn_av_norm<<<gAV, 256>>>(attn, pv, prm, pri, pc);

    dim3 gProj(DD / 128, MM / 128);                 // (8, 32)
    sgemm_bias_tc<<<gProj, 256, GEMM_SMEM_BYTES>>>(pc, Wo, bo, out, DD, DD);
}

// round 6
// speedup vs baseline: 1.8985x; 1.2969x over previous
#include <cuda_runtime.h>
#include <math.h>

#define BB 2
#define SS 2048
#define DD 1024
#define HH 16
#define DP 64
#define MM (BB * SS)   // 4096
#define NZ (BB * HH)   // 32
#define KT (SS / 128)  // 16 k-tiles per row

// Scratch (allocation-free rule: __device__ globals)
__device__ float g_q[MM * DD];
__device__ float g_k[MM * DD];
__device__ float g_v[MM * DD];
__device__ float g_c[MM * DD];
__device__ float g_rowm[NZ * SS];
__device__ float g_rowinv[NZ * SS];
__device__ float g_pm[(size_t)NZ * SS * KT];   // per (row, ktile) partial max
__device__ float g_ps[(size_t)NZ * SS * KT];   // per (row, ktile) partial sumexp

// ---------------------------------------------------------------------------
// Helpers
// ---------------------------------------------------------------------------
__device__ __forceinline__ unsigned f2tf(float x) {
    unsigned r;
    asm("cvt.rna.tf32.f32 %0, %1;" : "=r"(r) : "f"(x));
    return r;
}

__device__ __forceinline__ void mma8(float* c, const unsigned* a, const unsigned* b) {
    asm volatile(
        "mma.sync.aligned.m16n8k8.row.col.f32.tf32.tf32.f32 "
        "{%0,%1,%2,%3}, {%4,%5,%6,%7}, {%8,%9}, {%0,%1,%2,%3};"
        : "+f"(c[0]), "+f"(c[1]), "+f"(c[2]), "+f"(c[3])
        : "r"(a[0]), "r"(a[1]), "r"(a[2]), "r"(a[3]), "r"(b[0]), "r"(b[1]));
}

__device__ __forceinline__ unsigned smem_u32(const void* p) {
    unsigned r;
    asm("{ .reg .u64 t; cvta.to.shared.u64 t, %1; cvt.u32.u64 %0, t; }"
        : "=r"(r) : "l"(p));
    return r;
}

__device__ __forceinline__ void cpasync16(unsigned s, const void* g) {
    asm volatile("cp.async.cg.shared.global [%0], [%1], 16;" :: "r"(s), "l"(g));
}

// ---------------------------------------------------------------------------
// Pipelined tensor-core SGEMM + bias (round-5 proven): tile 128x128, K-tile 32,
// 2-stage cp.async double buffer.
// ---------------------------------------------------------------------------
#define AS_STR 36
#define BS_STR 136
#define STG_F  (128 * AS_STR + 32 * BS_STR)   // 8960 floats/stage

__device__ __forceinline__ void gemm_load_tile(const float* __restrict__ A,
                                               const float* __restrict__ W,
                                               int Kdim, int Ndim,
                                               int m0, int n0, int k0,
                                               float* stage) {
    const int tid = threadIdx.x;
    unsigned sA = smem_u32(stage);
    unsigned sB = smem_u32(stage + 128 * AS_STR);
    #pragma unroll
    for (int i = tid; i < 1024; i += 256) {
        int r = i >> 3, c4 = (i & 7) * 4;
        cpasync16(sA + (r * AS_STR + c4) * 4, A + (size_t)(m0 + r) * Kdim + k0 + c4);
    }
    #pragma unroll
    for (int i = tid; i < 1024; i += 256) {
        int r = i >> 5, c4 = (i & 31) * 4;
        cpasync16(sB + (r * BS_STR + c4) * 4, W + (size_t)(k0 + r) * Ndim + n0 + c4);
    }
    asm volatile("cp.async.commit_group;");
}

__device__ __forceinline__ void gemm_body(const float* __restrict__ A,
                                          const float* __restrict__ W,
                                          const float* __restrict__ bias,
                                          float* __restrict__ C,
                                          int Ndim, int Kdim,
                                          int m0, int n0,
                                          float* smf) {
    const int tid = threadIdx.x;
    const int warp = tid >> 5, lane = tid & 31;
    const int g = lane >> 2, t = lane & 3;
    const int wm = warp >> 1, wn = warp & 1;

    float acc[2][8][4] = {};

    gemm_load_tile(A, W, Kdim, Ndim, m0, n0, 0, smf);

    int s = 0;
    for (int k0 = 0; k0 < Kdim; k0 += 32, s ^= 1) {
        if (k0 + 32 < Kdim) {
            gemm_load_tile(A, W, Kdim, Ndim, m0, n0, k0 + 32, smf + (s ^ 1) * STG_F);
            asm volatile("cp.async.wait_group 1;");
        } else {
            asm volatile("cp.async.wait_group 0;");
        }
        __syncthreads();

        const float* As = smf + s * STG_F;
        const float* Bs = As + 128 * AS_STR;

        #pragma unroll
        for (int k = 0; k < 32; k += 8) {
            unsigned a[2][4], bfr[8][2];
            #pragma unroll
            for (int mt = 0; mt < 2; mt++) {
                int m = wm * 32 + mt * 16;
                a[mt][0] = f2tf(As[(m + g) * AS_STR + k + t]);
                a[mt][1] = f2tf(As[(m + g + 8) * AS_STR + k + t]);
                a[mt][2] = f2tf(As[(m + g) * AS_STR + k + t + 4]);
                a[mt][3] = f2tf(As[(m + g + 8) * AS_STR + k + t + 4]);
            }
            #pragma unroll
            for (int nt = 0; nt < 8; nt++) {
                int n = wn * 64 + nt * 8 + g;
                bfr[nt][0] = f2tf(Bs[(k + t) * BS_STR + n]);
                bfr[nt][1] = f2tf(Bs[(k + t + 4) * BS_STR + n]);
            }
            #pragma unroll
            for (int mt = 0; mt < 2; mt++)
                #pragma unroll
                for (int nt = 0; nt < 8; nt++)
                    mma8(acc[mt][nt], a[mt], bfr[nt]);
        }
        __syncthreads();
    }

    #pragma unroll
    for (int mt = 0; mt < 2; mt++) {
        int row = m0 + wm * 32 + mt * 16 + g;
        #pragma unroll
        for (int nt = 0; nt < 8; nt++) {
            int col = n0 + wn * 64 + nt * 8 + 2 * t;
            float b0 = bias[col], b1 = bias[col + 1];
            C[(size_t)row * Ndim + col]           = acc[mt][nt][0] + b0;
            C[(size_t)row * Ndim + col + 1]       = acc[mt][nt][1] + b1;
            C[(size_t)(row + 8) * Ndim + col]     = acc[mt][nt][2] + b0;
            C[(size_t)(row + 8) * Ndim + col + 1] = acc[mt][nt][3] + b1;
        }
    }
}

#define GEMM_SMEM_BYTES (2 * STG_F * 4)   // 71680

__global__ void sgemm_bias_tc(const float* __restrict__ A,
                              const float* __restrict__ W,
                              const float* __restrict__ bias,
                              float* __restrict__ C,
                              int Ndim, int Kdim) {
    extern __shared__ float smf[];
    gemm_body(A, W, bias, C, Ndim, Kdim, blockIdx.y * 128, blockIdx.x * 128, smf);
}

__global__ void qkv_gemm_tc(const float* __restrict__ A0, const float* __restrict__ A1,
                            const float* __restrict__ A2,
                            const float* __restrict__ W0, const float* __restrict__ W1,
                            const float* __restrict__ W2,
                            const float* __restrict__ b0, const float* __restrict__ b1,
                            const float* __restrict__ b2,
                            float* __restrict__ C0, float* __restrict__ C1,
                            float* __restrict__ C2) {
    extern __shared__ float smf[];
    const int z = blockIdx.z;
    const float* A = (z == 0) ? A0 : (z == 1) ? A1 : A2;
    const float* W = (z == 0) ? W0 : (z == 1) ? W1 : W2;
    const float* bs = (z == 0) ? b0 : (z == 1) ? b1 : b2;
    float* C = (z == 0) ? C0 : (z == 1) ? C1 : C2;
    gemm_body(A, W, bs, C, DD, DD, blockIdx.y * 128, blockIdx.x * 128, smf);
}

// ---------------------------------------------------------------------------
// Attention scores + per-tile partial softmax stats.
// Writes raw (scaled+masked) logits to attn, and per (row, ktile) partial
// max / sumexp to g_pm / g_ps.
// ---------------------------------------------------------------------------
#define QS_STR 68
#define SCORES_SMEM_BYTES (2 * 128 * QS_STR * 4)
__global__ void attn_scores_tc(const float* __restrict__ Q,
                               const float* __restrict__ K,
                               const float* __restrict__ mask,
                               float* __restrict__ attn,
                               float* __restrict__ pm,
                               float* __restrict__ ps) {
    extern __shared__ unsigned sm[];
    unsigned* Qs = sm;                  // [128][68]
    unsigned* Ks = sm + 128 * QS_STR;   // [128][68]
    __shared__ float pmax[128 * 2];
    __shared__ float psum[128 * 2];

    const int z = blockIdx.z;
    const int b = z >> 4;
    const int h = z & 15;
    const int q0 = blockIdx.y * 128, k0 = blockIdx.x * 128;
    const int ktile = blockIdx.x;
    const int tid = threadIdx.x;
    const int warp = tid >> 5, lane = tid & 31;
    const int g = lane >> 2, t = lane & 3;
    const int wm = warp >> 1, wn = warp & 1;

    const float* Qb = Q + (size_t)(b * SS + q0) * DD + h * DP;
    const float* Kb = K + (size_t)(b * SS + k0) * DD + h * DP;

    #pragma unroll
    for (int i = tid; i < 128 * 16; i += 256) {
        int r = i >> 4, c4 = (i & 15) * 4;
        float4 vq = *(const float4*)(Qb + (size_t)r * DD + c4);
        float4 vk = *(const float4*)(Kb + (size_t)r * DD + c4);
        Qs[r * QS_STR + c4 + 0] = f2tf(vq.x);
        Qs[r * QS_STR + c4 + 1] = f2tf(vq.y);
        Qs[r * QS_STR + c4 + 2] = f2tf(vq.z);
        Qs[r * QS_STR + c4 + 3] = f2tf(vq.w);
        Ks[r * QS_STR + c4 + 0] = f2tf(vk.x);
        Ks[r * QS_STR + c4 + 1] = f2tf(vk.y);
        Ks[r * QS_STR + c4 + 2] = f2tf(vk.z);
        Ks[r * QS_STR + c4 + 3] = f2tf(vk.w);
    }
    __syncthreads();

    float acc[2][8][4] = {};
    #pragma unroll
    for (int k = 0; k < 64; k += 8) {
        unsigned a[2][4], bfr[8][2];
        #pragma unroll
        for (int mt = 0; mt < 2; mt++) {
            int m = wm * 32 + mt * 16;
            a[mt][0] = Qs[(m + g) * QS_STR + k + t];
            a[mt][1] = Qs[(m + g + 8) * QS_STR + k + t];
            a[mt][2] = Qs[(m + g) * QS_STR + k + t + 4];
            a[mt][3] = Qs[(m + g + 8) * QS_STR + k + t + 4];
        }
        #pragma unroll
        for (int nt = 0; nt < 8; nt++) {
            int n = wn * 64 + nt * 8 + g;
            bfr[nt][0] = Ks[n * QS_STR + k + t];
            bfr[nt][1] = Ks[n * QS_STR + k + t + 4];
        }
        #pragma unroll
        for (int mt = 0; mt < 2; mt++)
            #pragma unroll
            for (int nt = 0; nt < 8; nt++)
                mma8(acc[mt][nt], a[mt], bfr[nt]);
    }

    // scale + mask in registers
    #pragma unroll
    for (int mt = 0; mt < 2; mt++)
        #pragma unroll
        for (int nt = 0; nt < 8; nt++) {
            int kj = k0 + wn * 64 + nt * 8 + 2 * t;
            float mk0 = mask[b * SS + kj] * (-1e9f);
            float mk1 = mask[b * SS + kj + 1] * (-1e9f);
            acc[mt][nt][0] = acc[mt][nt][0] * 0.125f + mk0;
            acc[mt][nt][1] = acc[mt][nt][1] * 0.125f + mk1;
            acc[mt][nt][2] = acc[mt][nt][2] * 0.125f + mk0;
            acc[mt][nt][3] = acc[mt][nt][3] * 0.125f + mk1;
        }

    // write raw logits
    #pragma unroll
    for (int mt = 0; mt < 2; mt++) {
        int qi = q0 + wm * 32 + mt * 16 + g;
        size_t base0 = ((size_t)z * SS + qi) * SS;
        size_t base1 = base0 + (size_t)8 * SS;
        #pragma unroll
        for (int nt = 0; nt < 8; nt++) {
            int kj = k0 + wn * 64 + nt * 8 + 2 * t;
            attn[base0 + kj]     = acc[mt][nt][0];
            attn[base0 + kj + 1] = acc[mt][nt][1];
            attn[base1 + kj]     = acc[mt][nt][2];
            attn[base1 + kj + 1] = acc[mt][nt][3];
        }
    }

    // ---- per-tile partial stats ----
    #pragma unroll
    for (int mt = 0; mt < 2; mt++)
        #pragma unroll
        for (int hi = 0; hi < 2; hi++) {
            float mx = -1e30f;
            #pragma unroll
            for (int nt = 0; nt < 8; nt++)
                mx = fmaxf(mx, fmaxf(acc[mt][nt][2 * hi], acc[mt][nt][2 * hi + 1]));
            mx = fmaxf(mx, __shfl_xor_sync(~0u, mx, 1));
            mx = fmaxf(mx, __shfl_xor_sync(~0u, mx, 2));
            if (t == 0) pmax[(wm * 32 + mt * 16 + 8 * hi + g) * 2 + wn] = mx;
        }
    __syncthreads();

    #pragma unroll
    for (int mt = 0; mt < 2; mt++)
        #pragma unroll
        for (int hi = 0; hi < 2; hi++) {
            int row = wm * 32 + mt * 16 + 8 * hi + g;
            float tm = fmaxf(pmax[row * 2], pmax[row * 2 + 1]);
            float ls = 0.f;
            #pragma unroll
            for (int nt = 0; nt < 8; nt++)
                ls += __expf(acc[mt][nt][2 * hi] - tm) +
                      __expf(acc[mt][nt][2 * hi + 1] - tm);
            ls += __shfl_xor_sync(~0u, ls, 1);
            ls += __shfl_xor_sync(~0u, ls, 2);
            if (t == 0) psum[row * 2 + wn] = ls;
        }
    __syncthreads();

    if (tid < 128) {
        float m = fmaxf(pmax[tid * 2], pmax[tid * 2 + 1]);
        float ssum = psum[tid * 2] + psum[tid * 2 + 1];
        size_t idx = ((size_t)z * SS + q0 + tid) * KT + ktile;
        pm[idx] = m;
        ps[idx] = ssum;
    }
}

// ---------------------------------------------------------------------------
// Combine partial stats -> rowm, rowinv. One warp per row (8 rows/block).
// ---------------------------------------------------------------------------
__global__ void combine_stats(const float* __restrict__ pm,
                              const float* __restrict__ ps,
                              float* __restrict__ rowm,
                              float* __restrict__ rowinv) {
    const int w = threadIdx.x >> 5, lane = threadIdx.x & 31;
    const size_t row = (size_t)blockIdx.x * 8 + w;
    float m = (lane < KT) ? pm[row * KT + lane] : -1e30f;
    float s = (lane < KT) ? ps[row * KT + lane] : 0.f;
    float M = m;
    #pragma unroll
    for (int o = 8; o; o >>= 1) M = fmaxf(M, __shfl_xor_sync(~0u, M, o));
    float S = s * __expf(m - M);
    #pragma unroll
    for (int o = 8; o; o >>= 1) S += __shfl_xor_sync(~0u, S, o);
    if (lane == 0) {
        rowm[row] = M;
        rowinv[row] = 1.0f / S;
    }
}

// ---------------------------------------------------------------------------
// Fused normalize + AV, v2: K-tile 128, 2-stage cp.async double buffer.
// Stage: raw attn tile [128][132] (f32, overwritten in place with tf32 p)
//        + V tile [128][72] (f32 -> read as f32, cvt at fragment load).
// Block: 128 q x 64 d. 8 warps 4x2, warp tile 32q x 32d.
// ---------------------------------------------------------------------------
#define PS_STR 132
#define VS_STR 72
#define AV_STG_F (128 * PS_STR + 128 * VS_STR)   // 26112 floats/stage
#define AV_SMEM_BYTES (2 * AV_STG_F * 4)         // 208896

__device__ __forceinline__ void av_load_tile(const float* __restrict__ attn,
                                             const float* __restrict__ V,
                                             int z, int b, int h, int q0, int k0,
                                             float* stage) {
    const int tid = threadIdx.x;
    unsigned sP = smem_u32(stage);
    unsigned sV = smem_u32(stage + 128 * PS_STR);
    #pragma unroll
    for (int i = tid; i < 4096; i += 256) {       // 128 x 128 floats
        int r = i >> 5, c4 = (i & 31) * 4;
        cpasync16(sP + (r * PS_STR + c4) * 4,
                  attn + ((size_t)z * SS + q0 + r) * SS + k0 + c4);
    }
    #pragma unroll
    for (int i = tid; i < 2048; i += 256) {       // 128 x 64 floats
        int r = i >> 4, c4 = (i & 15) * 4;
        cpasync16(sV + (r * VS_STR + c4) * 4,
                  V + (size_t)(b * SS + k0 + r) * DD + h * DP + c4);
    }
    asm volatile("cp.async.commit_group;");
}

__global__ void attn_av_norm(float* __restrict__ attn,
                             const float* __restrict__ V,
                             const float* __restrict__ rowm,
                             const float* __restrict__ rowinv,
                             float* __restrict__ C) {
    extern __shared__ float smf[];
    __shared__ float rs[128], ri[128];

    const int z = blockIdx.y;
    const int b = z >> 4;
    const int h = z & 15;
    const int q0 = blockIdx.x * 128;
    const int tid = threadIdx.x;
    const int warp = tid >> 5, lane = tid & 31;
    const int g = lane >> 2, t = lane & 3;
    const int wm = warp >> 1, wn = warp & 1;

    if (tid < 128) {
        rs[tid] = rowm[(size_t)z * SS + q0 + tid];
        ri[tid] = rowinv[(size_t)z * SS + q0 + tid];
    }

    av_load_tile(attn, V, z, b, h, q0, 0, smf);

    float acc[2][4][4] = {};
    int s = 0;
    for (int k0 = 0; k0 < SS; k0 += 128, s ^= 1) {
        if (k0 + 128 < SS) {
            av_load_tile(attn, V, z, b, h, q0, k0 + 128, smf + (s ^ 1) * AV_STG_F);
            asm volatile("cp.async.wait_group 1;");
        } else {
            asm volatile("cp.async.wait_group 0;");
        }
        __syncthreads();

        float* stage = smf + s * AV_STG_F;
        unsigned* stage_u = (unsigned*)stage;
        const float* Vs = stage + 128 * PS_STR;

        // exp + normalize: in-place f32 -> tf32, plus global write
        #pragma unroll
        for (int i = tid; i < 4096; i += 256) {
            int r = i >> 5, c4 = (i & 31) * 4;
            float4 x = *(float4*)(stage + r * PS_STR + c4);
            float m = rs[r], inv = ri[r];
            x.x = __expf(x.x - m) * inv;
            x.y = __expf(x.y - m) * inv;
            x.z = __expf(x.z - m) * inv;
            x.w = __expf(x.w - m) * inv;
            *(float4*)(attn + ((size_t)z * SS + q0 + r) * SS + k0 + c4) = x;
            stage_u[r * PS_STR + c4 + 0] = f2tf(x.x);
            stage_u[r * PS_STR + c4 + 1] = f2tf(x.y);
            stage_u[r * PS_STR + c4 + 2] = f2tf(x.z);
            stage_u[r * PS_STR + c4 + 3] = f2tf(x.w);
        }
        __syncthreads();

        #pragma unroll
        for (int kk = 0; kk < 128; kk += 8) {
            unsigned a[2][4], bfr[4][2];
            #pragma unroll
            for (int mt = 0; mt < 2; mt++) {
                int m = wm * 32 + mt * 16;
                a[mt][0] = stage_u[(m + g) * PS_STR + kk + t];
                a[mt][1] = stage_u[(m + g + 8) * PS_STR + kk + t];
                a[mt][2] = stage_u[(m + g) * PS_STR + kk + t + 4];
                a[mt][3] = stage_u[(m + g + 8) * PS_STR + kk + t + 4];
            }
            #pragma unroll
            for (int nt = 0; nt < 4; nt++) {
                int n = wn * 32 + nt * 8 + g;
                bfr[nt][0] = f2tf(Vs[(kk + t) * VS_STR + n]);
                bfr[nt][1] = f2tf(Vs[(kk + t + 4) * VS_STR + n]);
            }
            #pragma unroll
            for (int mt = 0; mt < 2; mt++)
                #pragma unroll
                for (int nt = 0; nt < 4; nt++)
                    mma8(acc[mt][nt], a[mt], bfr[nt]);
        }
        __syncthreads();
    }

    #pragma unroll
    for (int mt = 0; mt < 2; mt++) {
        int qi = q0 + wm * 32 + mt * 16 + g;
        size_t base0 = (size_t)(b * SS + qi) * DD + h * DP;
        size_t base1 = base0 + (size_t)8 * DD;
        #pragma unroll
        for (int nt = 0; nt < 4; nt++) {
            int dj = wn * 32 + nt * 8 + 2 * t;
            C[base0 + dj]     = acc[mt][nt][0];
            C[base0 + dj + 1] = acc[mt][nt][1];
            C[base1 + dj]     = acc[mt][nt][2];
            C[base1 + dj + 1] = acc[mt][nt][3];
        }
    }
}

// ---------------------------------------------------------------------------
extern "C" void kernel_launch(void* const* d_in, const int* in_sizes, int n_in,
                              void* d_out, int out_size) {
    const float* q    = (const float*)d_in[0];
    const float* k    = (const float*)d_in[1];
    const float* v    = (const float*)d_in[2];
    const float* mask = (const float*)d_in[3];
    const float* Wq   = (const float*)d_in[4];
    const float* bq   = (const float*)d_in[5];
    const float* Wk   = (const float*)d_in[6];
    const float* bk   = (const float*)d_in[7];
    const float* Wv   = (const float*)d_in[8];
    const float* bv   = (const float*)d_in[9];
    const float* Wo   = (const float*)d_in[10];
    const float* bo   = (const float*)d_in[11];

    float* out  = (float*)d_out;
    float* attn = out + (size_t)MM * DD;   // output layout: (out, attn)

    float *pq, *pk, *pv, *pc, *prm, *pri, *ppm, *pps;
    cudaGetSymbolAddress((void**)&pq, g_q);
    cudaGetSymbolAddress((void**)&pk, g_k);
    cudaGetSymbolAddress((void**)&pv, g_v);
    cudaGetSymbolAddress((void**)&pc, g_c);
    cudaGetSymbolAddress((void**)&prm, g_rowm);
    cudaGetSymbolAddress((void**)&pri, g_rowinv);
    cudaGetSymbolAddress((void**)&ppm, g_pm);
    cudaGetSymbolAddress((void**)&pps, g_ps);

    cudaFuncSetAttribute(qkv_gemm_tc, cudaFuncAttributeMaxDynamicSharedMemorySize,
                         GEMM_SMEM_BYTES);
    cudaFuncSetAttribute(sgemm_bias_tc, cudaFuncAttributeMaxDynamicSharedMemorySize,
                         GEMM_SMEM_BYTES);
    cudaFuncSetAttribute(attn_scores_tc, cudaFuncAttributeMaxDynamicSharedMemorySize,
                         SCORES_SMEM_BYTES);
    cudaFuncSetAttribute(attn_av_norm, cudaFuncAttributeMaxDynamicSharedMemorySize,
                         AV_SMEM_BYTES);

    dim3 gQKV(DD / 128, MM / 128, 3);               // (8, 32, 3)
    qkv_gemm_tc<<<gQKV, 256, GEMM_SMEM_BYTES>>>(q, k, v, Wq, Wk, Wv, bq, bk, bv,
                                                pq, pk, pv);

    dim3 gScores(SS / 128, SS / 128, NZ);           // (16, 16, 32)
    attn_scores_tc<<<gScores, 256, SCORES_SMEM_BYTES>>>(pq, pk, mask, attn, ppm, pps);

    combine_stats<<<NZ * SS / 8, 256>>>(ppm, pps, prm, pri);

    dim3 gAV(SS / 128, NZ);                         // (16, 32)
    attn_av_norm<<<gAV, 256, AV_SMEM_BYTES>>>(attn, pv, prm, pri, pc);

    dim3 gProj(DD / 128, MM / 128);                 // (8, 32)
    sgemm_bias_tc<<<gProj, 256, GEMM_SMEM_BYTES>>>(pc, Wo, bo, out, DD, DD);
}